// round 16
// baseline (speedup 1.0000x reference)
#include <cuda_runtime.h>
#include <cuda_fp16.h>
#include <math.h>
#include <stdint.h>

#define BDIM 8
#define TDIM 8192
#define BT (BDIM*TDIM)
#define HDIM 512
#define SSDIM 32

typedef unsigned long long u64;

// ---------------- scratch (device globals; no allocations allowed) ----------
__device__ float g_gates[BDIM*SSDIM*TDIM];
__device__ float g_drive[BDIM*SSDIM*TDIM];
__device__ float g_states[BDIM*SSDIM*TDIM];
// fp16 activations
__device__ __half g_hh[(size_t)BT*512];     // fp16 h (post-Win silu)
__device__ __half g_xh[(size_t)BT*512];     // ln output / MLP ping
__device__ __half g_x2h[(size_t)BT*512];    // MLP pong
__device__ __half g_feat[(size_t)BT*192];   // features padded to 192
// fp16 transposed weights
__device__ __half g_wh[4][512*512];         // MLP x3 + Wout
__device__ __half g_wf[512*192];            // Win transposed+padded
__device__ __half g_wgi[64*512];            // [Wg|Wi] interleaved cols

__device__ __forceinline__ float silu_f(float x) { return x / (1.f + __expf(-x)); }

__device__ __forceinline__ u64 pack2(float x) {
    u64 r; asm("mov.b64 %0, {%1, %1};" : "=l"(r) : "f"(x)); return r;
}
__device__ __forceinline__ void ffma2(u64& d, u64 a, u64 b) {
    asm("fma.rn.f32x2 %0, %1, %2, %3;" : "=l"(d) : "l"(a), "l"(b), "l"(d));
}
__device__ __forceinline__ float lo32(u64 v) { return __uint_as_float((unsigned)v); }
__device__ __forceinline__ float hi32(u64 v) { return __uint_as_float((unsigned)(v >> 32)); }

// ---------------- mma.sync / async helpers (arch-agnostic, sm_80+) ----------
__device__ __forceinline__ uint32_t smem_u32(const void* p) {
    uint32_t a;
    asm("{ .reg .u64 t; cvta.to.shared.u64 t, %1; cvt.u32.u64 %0, t; }" : "=r"(a) : "l"(p));
    return a;
}
#define CP_COMMIT()      asm volatile("cp.async.commit_group;" ::: "memory")
#define CP_WAIT1()       asm volatile("cp.async.wait_group 1;" ::: "memory")
#define CP_WAIT0()       asm volatile("cp.async.wait_group 0;" ::: "memory")

__device__ __forceinline__ void cpasync16(uint32_t dst, const void* src) {
    asm volatile("cp.async.cg.shared.global [%0], [%1], 16;" :: "r"(dst), "l"(src));
}
__device__ __forceinline__ void ldmx4(uint32_t* r, uint32_t addr) {
    asm volatile("ldmatrix.sync.aligned.m8n8.x4.shared.b16 {%0,%1,%2,%3}, [%4];"
        : "=r"(r[0]), "=r"(r[1]), "=r"(r[2]), "=r"(r[3]) : "r"(addr));
}
__device__ __forceinline__ void mma16816(float* c, const uint32_t* a,
                                         uint32_t b0, uint32_t b1) {
    asm volatile("mma.sync.aligned.m16n8k16.row.col.f32.f16.f16.f32 "
        "{%0,%1,%2,%3}, {%4,%5,%6,%7}, {%8,%9}, {%0,%1,%2,%3};"
        : "+f"(c[0]), "+f"(c[1]), "+f"(c[2]), "+f"(c[3])
        : "r"(a[0]), "r"(a[1]), "r"(a[2]), "r"(a[3]), "r"(b0), "r"(b1));
}
__device__ __forceinline__ uint32_t tile_addr(uint32_t tbase, int row, int c16) {
    return tbase + row * 128 + ((c16 ^ (row & 7)) << 4);
}

// ---------------------------------------------------------------------------
// K1: FUSED hash/scale-attention + conv/emb/match features -> fp16 g_feat
// block = 32 output tokens; computes 35 haloed hf rows into smem.
// ---------------------------------------------------------------------------
__global__ void __launch_bounds__(256) k_hfeat(
    const int* __restrict__ chars, const float* __restrict__ emb_byte,
    const float* __restrict__ htab, const float* __restrict__ Wq,
    const float* __restrict__ bq,
    const float* __restrict__ conv_w, const float* __restrict__ conv_b)
{
    __shared__ float shf[35 * 64];
    __shared__ float s_be[8][64];
    __shared__ int sch[32];
    int blk = blockIdx.x;
    int b = blk / (TDIM / 32);
    int tBase = (blk % (TDIM / 32)) * 32;
    int tid = threadIdx.x;
    int w = tid >> 5, lane = tid & 31;
    const int* cb = chars + b * TDIM;

    if (tid < 32) sch[tid] = cb[tBase + tid];

    int c0 = lane * 2;
#pragma unroll 1
    for (int it = 0; it < 5; it++) {
        int s = w + it * 8;
        if (s >= 35) break;
        int t = tBase - 3 + s;
        if (t < 0) {
            *(float2*)&shf[s * 64 + c0] = make_float2(0.f, 0.f);
            continue;
        }
        int myc = (lane < 16 && t >= lane) ? cb[t - lane] : 0;
        int acc0 = 0, acc1 = 0, acc2 = 0, acc3 = 0;
        int p = 1;
#pragma unroll
        for (int j = 0; j < 16; j++) {
            int cj = __shfl_sync(0xffffffffu, myc, j);
            int term = cj * p;
            if (j < 2) acc0 += term;
            if (j < 4) acc1 += term;
            if (j < 8) acc2 += term;
            acc3 += term;
            p = (p * 257) & 4095;
        }
        int h0 = acc0 & 4095, h1 = acc1 & 4095, h2 = acc2 & 4095, h3 = acc3 & 4095;

        int ch0 = __shfl_sync(0xffffffffu, myc, 0);
        float2 be = *(const float2*)&emb_byte[ch0 * 64 + c0];
        s_be[w][c0]     = be.x;
        s_be[w][c0 + 1] = be.y;
        __syncwarp();

        float q0 = bq[c0], q1 = bq[c0 + 1];
#pragma unroll 8
        for (int k = 0; k < 64; k++) {
            float bk = s_be[w][k];
            float2 wv = *(const float2*)&Wq[k * 64 + c0];
            q0 = fmaf(bk, wv.x, q0);
            q1 = fmaf(bk, wv.y, q1);
        }
        __syncwarp();

        float2 se0 = *(const float2*)&htab[(size_t)(0 * 4096 + h0) * 64 + c0];
        float2 se1 = *(const float2*)&htab[(size_t)(1 * 4096 + h1) * 64 + c0];
        float2 se2 = *(const float2*)&htab[(size_t)(2 * 4096 + h2) * 64 + c0];
        float2 se3 = *(const float2*)&htab[(size_t)(3 * 4096 + h3) * 64 + c0];

        float s0 = q0 * se0.x + q1 * se0.y;
        float s1 = q0 * se1.x + q1 * se1.y;
        float s2 = q0 * se2.x + q1 * se2.y;
        float s3 = q0 * se3.x + q1 * se3.y;
#pragma unroll
        for (int off = 16; off; off >>= 1) {
            s0 += __shfl_xor_sync(0xffffffffu, s0, off);
            s1 += __shfl_xor_sync(0xffffffffu, s1, off);
            s2 += __shfl_xor_sync(0xffffffffu, s2, off);
            s3 += __shfl_xor_sync(0xffffffffu, s3, off);
        }
        s0 *= 0.125f; s1 *= 0.125f; s2 *= 0.125f; s3 *= 0.125f;
        float m = fmaxf(fmaxf(s0, s1), fmaxf(s2, s3));
        float e0 = __expf(s0 - m), e1 = __expf(s1 - m), e2 = __expf(s2 - m), e3 = __expf(s3 - m);
        float inv = 1.f / (e0 + e1 + e2 + e3);
        float o0 = (e0 * se0.x + e1 * se1.x + e2 * se2.x + e3 * se3.x) * inv;
        float o1 = (e0 * se0.y + e1 * se1.y + e2 * se2.y + e3 * se3.y) * inv;
        *(float2*)&shf[s * 64 + c0] = make_float2(o0, o1);
    }
    __syncthreads();

    // byte emb -> cols 0..63
    for (int idx = tid; idx < 32 * 64; idx += 256) {
        int tok = idx >> 6, c = idx & 63;
        g_feat[(size_t)(b * TDIM + tBase + tok) * 192 + c] =
            __float2half_rn(emb_byte[sch[tok] * 64 + c]);
    }
    // causal conv + silu from smem halo -> cols 64..127
    for (int idx = tid; idx < 32 * 64; idx += 256) {
        int tok = idx >> 6, c = idx & 63;
        float acc = conv_b[c];
#pragma unroll
        for (int k = 0; k < 4; k++)
            acc = fmaf(conv_w[c * 4 + k], shf[(tok + k) * 64 + c], acc);
        g_feat[(size_t)(b * TDIM + tBase + tok) * 192 + 64 + c] =
            __float2half_rn(silu_f(acc));
    }
    // match feats + zero pad -> cols 128..191
    for (int idx = tid; idx < 32 * 64; idx += 256) {
        int tok = idx >> 6, m = idx & 63;
        int t = tBase + tok;
        float v = 0.f;
        if (m < 4) {
            int k = 1 << m;
            if (t >= k) v = (cb[t] == cb[t - k]) ? 1.f : 0.f;
        }
        g_feat[(size_t)(b * TDIM + t) * 192 + 128 + m] = __float2half_rn(v);
    }
}

// ---------------------------------------------------------------------------
// K4: chunk-parallel TinyScan (verified)
// ---------------------------------------------------------------------------
__global__ void __launch_bounds__(256) k_scan()
{
    int bs = blockIdx.x;
    int j = threadIdx.x;
    const float* ga = g_gates + (size_t)bs * TDIM + j * 32;
    const float* dr = g_drive + (size_t)bs * TDIM + j * 32;
    float a[32], bb[32];
#pragma unroll
    for (int i = 0; i < 32; i++) {
        a[i]  = fmaxf(ga[i], 1e-6f);
        bb[i] = dr[i];
    }
    float cumA = 1.f, cumWB = 0.f;
#pragma unroll
    for (int i = 0; i < 32; i++) {
        cumA *= a[i];
        float inv = 1.f / fmaxf(cumA, 1e-8f);
        cumWB = fmaf(bb[i], inv, cumWB);
    }
    __shared__ float sA[256], sB[256];
    sA[j] = cumA;
    sB[j] = cumA * cumWB;
    __syncthreads();
    for (int d = 1; d < 256; d <<= 1) {
        float a2 = sA[j], b2 = sB[j], a1 = 0.f, b1 = 0.f;
        if (j >= d) { a1 = sA[j - d]; b1 = sB[j - d]; }
        __syncthreads();
        if (j >= d) { sA[j] = a2 * a1; sB[j] = fmaf(a2, b1, b2); }
        __syncthreads();
    }
    float hc = (j == 0) ? 0.f : sB[j - 1];
    cumA = 1.f; cumWB = 0.f;
    float* st = g_states + (size_t)bs * TDIM + j * 32;
#pragma unroll
    for (int i = 0; i < 32; i++) {
        cumA *= a[i];
        float inv = 1.f / fmaxf(cumA, 1e-8f);
        cumWB = fmaf(bb[i], inv, cumWB);
        st[i] = cumA * (hc + cumWB);
    }
}

// ---------------------------------------------------------------------------
// K5: fused y = hh + states@Wo + bo, LayerNorm, write fp16 g_xh.
// residual read from fp16 g_hh.
// ---------------------------------------------------------------------------
#define WOLN_SMEM (32*32*4 + 32*520*4)
__global__ void __launch_bounds__(256) k_wo_ln(
    const float* __restrict__ Wo, const float* __restrict__ bo,
    const float* __restrict__ lng, const float* __restrict__ lnb)
{
    extern __shared__ float dyn[];
    float (*sxt)[32] = (float(*)[32])dyn;
    float* sy = dyn + 32 * 32;
    int tid = threadIdx.x;
    int n0 = blockIdx.x * 32;
    int b = n0 / TDIM, t0 = n0 % TDIM;

    for (int i = tid; i < 32 * 8; i += 256) {
        int s = i >> 3, t4 = (i & 7) * 4;
        float4 v = *(const float4*)&g_states[(size_t)(b * SSDIM + s) * TDIM + t0 + t4];
        *(float4*)&sxt[s][t4] = v;
    }
    __syncthreads();

    u64 acc[16][2];
#pragma unroll
    for (int i = 0; i < 16; i++) { acc[i][0] = 0ull; acc[i][1] = 0ull; }

#pragma unroll 1
    for (int k4 = 0; k4 < 32; k4 += 4) {
        u64 wp[4][2];
#pragma unroll
        for (int j = 0; j < 4; j++) {
            wp[j][0] = pack2(Wo[(size_t)(k4 + j) * 512 + tid]);
            wp[j][1] = pack2(Wo[(size_t)(k4 + j) * 512 + tid + 256]);
        }
#pragma unroll
        for (int j = 0; j < 4; j++) {
            const ulonglong2* xr = (const ulonglong2*)&sxt[k4 + j][0];
#pragma unroll
            for (int q = 0; q < 8; q++) {
                ulonglong2 x2 = xr[q];
                ffma2(acc[2 * q][0],     x2.x, wp[j][0]);
                ffma2(acc[2 * q][1],     x2.x, wp[j][1]);
                ffma2(acc[2 * q + 1][0], x2.y, wp[j][0]);
                ffma2(acc[2 * q + 1][1], x2.y, wp[j][1]);
            }
        }
    }
#pragma unroll
    for (int cc = 0; cc < 2; cc++) {
        int col = tid + cc * 256;
        float bv = bo[col];
#pragma unroll
        for (int p = 0; p < 16; p++) {
            size_t r0 = (size_t)(n0 + 2 * p) * 512 + col;
            sy[(2 * p) * 520 + col]     = lo32(acc[p][cc]) + bv + __half2float(g_hh[r0]);
            sy[(2 * p + 1) * 520 + col] = hi32(acc[p][cc]) + bv + __half2float(g_hh[r0 + 512]);
        }
    }
    __syncthreads();

    int wid = tid >> 5, lane = tid & 31;
#pragma unroll
    for (int q = 0; q < 4; q++) {
        int tok = wid * 4 + q;
        const float* row = sy + tok * 520;
        float4 v[4];
        float lsum = 0.f, lsq = 0.f;
#pragma unroll
        for (int i = 0; i < 4; i++) {
            v[i] = *(const float4*)&row[lane * 16 + i * 4];
            lsum += v[i].x + v[i].y + v[i].z + v[i].w;
            lsq  += v[i].x * v[i].x + v[i].y * v[i].y + v[i].z * v[i].z + v[i].w * v[i].w;
        }
#pragma unroll
        for (int off = 16; off; off >>= 1) {
            lsum += __shfl_xor_sync(0xffffffffu, lsum, off);
            lsq  += __shfl_xor_sync(0xffffffffu, lsq,  off);
        }
        float mu = lsum * (1.f / 512.f);
        float var = lsq * (1.f / 512.f) - mu * mu;
        float rstd = rsqrtf(var + 1e-5f);
        __half hh[16];
#pragma unroll
        for (int i = 0; i < 4; i++) {
            float4 g4 = *(const float4*)&lng[lane * 16 + i * 4];
            float4 b4 = *(const float4*)&lnb[lane * 16 + i * 4];
            hh[i * 4 + 0] = __float2half_rn((v[i].x - mu) * rstd * g4.x + b4.x);
            hh[i * 4 + 1] = __float2half_rn((v[i].y - mu) * rstd * g4.y + b4.y);
            hh[i * 4 + 2] = __float2half_rn((v[i].z - mu) * rstd * g4.z + b4.z);
            hh[i * 4 + 3] = __float2half_rn((v[i].w - mu) * rstd * g4.w + b4.w);
        }
        *(int4*)&g_xh[(size_t)(n0 + tok) * 512 + lane * 16]     = *(int4*)&hh[0];
        *(int4*)&g_xh[(size_t)(n0 + tok) * 512 + lane * 16 + 8] = *(int4*)&hh[8];
    }
}

// ---------------------------------------------------------------------------
// Weight prep
// ---------------------------------------------------------------------------
__global__ void __launch_bounds__(256) k_prep_w(
    const float* __restrict__ W, int N, int layer)
{
    int idx = blockIdx.x * 256 + threadIdx.x;
    int k = idx & 511;
    int n = idx >> 9;
    if (n >= N) return;
    float w = W[(size_t)k * N + n];
    g_wh[layer][(size_t)n * 512 + k] = __float2half_rn(w);
}
__global__ void __launch_bounds__(256) k_prep_wf(const float* __restrict__ Win)
{
    int idx = blockIdx.x * 256 + threadIdx.x;
    int k = idx % 192;
    int n = idx / 192;
    if (n >= 512) return;
    float w = (k < 132) ? Win[(size_t)k * 512 + n] : 0.f;
    g_wf[(size_t)n * 192 + k] = __float2half_rn(w);
}
__global__ void __launch_bounds__(256) k_prep_wgi(
    const float* __restrict__ Wg, const float* __restrict__ Wi)
{
    int idx = blockIdx.x * 256 + threadIdx.x;
    int k = idx & 511;
    int n = idx >> 9;
    if (n >= 64) return;
    float w = (n & 1) ? Wi[(size_t)k * 32 + (n >> 1)] : Wg[(size_t)k * 32 + (n >> 1)];
    g_wgi[(size_t)n * 512 + k] = __float2half_rn(w);
}

// ---------------------------------------------------------------------------
// fp16 1-term mma.sync GEMM: D = X16@W16' (fp32 accum)
// CTA: 256xNc128xK(KDIM); 8 warps 4x2, warp tile 64x64.
// 3-stage cp.async pipeline, 1 barrier/iter (48KB/stage, 144KB total).
// EPI: 0 = v+bias -> yf f32 (stride NOUT)                 [Wout]
//      1 = fp16resid + silu(v+bias) -> yh fp16            [MLP layers]
//      2 = silu(v+bias) -> yh fp16                        [Win]
// ---------------------------------------------------------------------------
#define STAGE_BYTES 49152
#define SMEM_MM (3 * STAGE_BYTES)

template<int KDIM, int NKT, int NOUT, int EPI>
__global__ void __launch_bounds__(256) k_mma(
    const __half* __restrict__ xh,
    const __half* __restrict__ wh,
    const float* __restrict__ bias,
    float* __restrict__ yf, __half* __restrict__ yh)
{
    extern __shared__ char dsm[];
    uint32_t smem0 = smem_u32(dsm);
    int tid = threadIdx.x;
    int wid = tid >> 5, lane = tid & 31;
    int wm = wid >> 1, wn = wid & 1;
    int n0 = blockIdx.x * 128;
    int m0 = blockIdx.y * 256;

    float c[4][8][4];
#pragma unroll
    for (int i = 0; i < 4; i++)
#pragma unroll
        for (int j = 0; j < 8; j++)
#pragma unroll
            for (int e = 0; e < 4; e++) c[i][j][e] = 0.f;

    auto fill = [&](int kt) {
        int stage = kt % 3;
        int kb = kt * 64;
        uint32_t sb = smem0 + stage * STAGE_BYTES;
#pragma unroll
        for (int j = 0; j < 12; j++) {
            int cidx = tid + 256 * j;
            const __half* src;
            uint32_t toff;
            int idx;
            if (cidx < 2048) { idx = cidx;        toff = 0;     src = xh + (size_t)(m0 + (idx >> 3)) * KDIM; }
            else             { idx = cidx - 2048; toff = 32768; src = wh + (size_t)(n0 + (idx >> 3)) * KDIM; }
            int row = idx >> 3;
            int c16 = idx & 7;
            uint32_t dst = sb + toff + row * 128 + ((c16 ^ (row & 7)) << 4);
            cpasync16(dst, (const void*)(src + kb + c16 * 8));
        }
        CP_COMMIT();
    };

    fill(0);
    fill(1);

    int la = lane & 15, lh = lane >> 4;

    for (int i = 0; i < NKT; i++) {
        uint32_t sb = smem0 + (i % 3) * STAGE_BYTES;
        if (i < NKT - 1) { CP_WAIT1(); } else { CP_WAIT0(); }
        __syncthreads();
        if (i + 2 < NKT) fill(i + 2);

#pragma unroll
        for (int kc = 0; kc < 4; kc++) {
            int c16 = kc * 2 + lh;
            uint32_t ah[4][4];
#pragma unroll
            for (int mt = 0; mt < 4; mt++)
                ldmx4(ah[mt], tile_addr(sb, wm * 64 + mt * 16 + la, c16));
#pragma unroll
            for (int hb = 0; hb < 2; hb++) {
                uint32_t bhf[2][4];
#pragma unroll
                for (int g = 0; g < 2; g++)
                    ldmx4(bhf[g], tile_addr(sb + 32768, wn * 64 + (hb * 2 + g) * 16 + la, c16));
#pragma unroll
                for (int mt = 0; mt < 4; mt++) {
#pragma unroll
                    for (int nt = 0; nt < 4; nt++) {
                        int g = nt >> 1, h = nt & 1;
                        mma16816(c[mt][hb * 4 + nt], ah[mt], bhf[g][h], bhf[g][2 + h]);
                    }
                }
            }
        }
    }

    int r0 = lane >> 2;
    int cp = (lane & 3) * 2;
#pragma unroll
    for (int nt = 0; nt < 8; nt++) {
        int col = n0 + wn * 64 + nt * 8 + cp;
        float2 bv = *(const float2*)&bias[col];
#pragma unroll
        for (int mt = 0; mt < 4; mt++) {
#pragma unroll
            for (int half = 0; half < 2; half++) {
                int row = m0 + wm * 64 + mt * 16 + r0 + half * 8;
                float v0 = c[mt][nt][2 * half]     + bv.x;
                float v1 = c[mt][nt][2 * half + 1] + bv.y;
                if (EPI == 1) {
                    __half2 xr = *(const __half2*)&xh[(size_t)row * KDIM + col];
                    v0 = __half2float(xr.x) + silu_f(v0);
                    v1 = __half2float(xr.y) + silu_f(v1);
                    __half2 hp;
                    hp.x = __float2half_rn(v0);
                    hp.y = __float2half_rn(v1);
                    *(__half2*)&yh[(size_t)row * 512 + col] = hp;
                } else if (EPI == 2) {
                    v0 = silu_f(v0);
                    v1 = silu_f(v1);
                    __half2 hp;
                    hp.x = __float2half_rn(v0);
                    hp.y = __float2half_rn(v1);
                    *(__half2*)&yh[(size_t)row * 512 + col] = hp;
                } else {
                    *(float2*)&yf[(size_t)row * NOUT + col] = make_float2(v0, v1);
                }
            }
        }
    }
}

// ---------------------------------------------------------------------------
// Gates MMA: hh[BT,512] @ wgi[64,512]' -> sigmoid/drive -> (B,S,T) layout
// 3-stage pipeline, 4 warps.
// ---------------------------------------------------------------------------
#define GSTG (32768 + 8192)
#define SMEM_G (3 * GSTG)
__global__ void __launch_bounds__(128) k_mma_g(
    const __half* __restrict__ xh,
    const float* __restrict__ bg, const float* __restrict__ bi)
{
    extern __shared__ char dsm[];
    uint32_t smem0 = smem_u32(dsm);
    int tid = threadIdx.x;
    int wid = tid >> 5, lane = tid & 31;
    int m0 = blockIdx.x * 256;
    int b = m0 / TDIM, t0 = m0 % TDIM;

    float c[4][8][4];
#pragma unroll
    for (int i = 0; i < 4; i++)
#pragma unroll
        for (int j = 0; j < 8; j++)
#pragma unroll
            for (int e = 0; e < 4; e++) c[i][j][e] = 0.f;

    auto fill = [&](int kt) {
        int stage = kt % 3;
        int kb = kt * 64;
        uint32_t sb = smem0 + stage * GSTG;
#pragma unroll
        for (int j = 0; j < 20; j++) {
            int cidx = tid + 128 * j;
            const __half* src;
            uint32_t toff;
            int idx;
            if (cidx < 2048) { idx = cidx;        toff = 0;     src = xh + (size_t)(m0 + (idx >> 3)) * 512; }
            else             { idx = cidx - 2048; toff = 32768; src = g_wgi + (size_t)(idx >> 3) * 512; }
            int row = idx >> 3;
            int c16 = idx & 7;
            uint32_t dst = sb + toff + row * 128 + ((c16 ^ (row & 7)) << 4);
            cpasync16(dst, (const void*)(src + kb + c16 * 8));
        }
        CP_COMMIT();
    };

    fill(0);
    fill(1);

    int la = lane & 15, lh = lane >> 4;

    for (int i = 0; i < 8; i++) {
        uint32_t sb = smem0 + (i % 3) * GSTG;
        if (i < 7) { CP_WAIT1(); } else { CP_WAIT0(); }
        __syncthreads();
        if (i + 2 < 8) fill(i + 2);

#pragma unroll
        for (int kc = 0; kc < 4; kc++) {
            int c16 = kc * 2 + lh;
            uint32_t ah[4][4];
#pragma unroll
            for (int mt = 0; mt < 4; mt++)
                ldmx4(ah[mt], tile_addr(sb, wid * 64 + mt * 16 + la, c16));
            uint32_t bhf[4][4];
#pragma unroll
            for (int g = 0; g < 4; g++)
                ldmx4(bhf[g], tile_addr(sb + 32768, g * 16 + la, c16));
#pragma unroll
            for (int mt = 0; mt < 4; mt++) {
#pragma unroll
                for (int nt = 0; nt < 8; nt++) {
                    int g = nt >> 1, h = nt & 1;
                    mma16816(c[mt][nt], ah[mt], bhf[g][h], bhf[g][2 + h]);
                }
            }
        }
    }

    int r0 = lane >> 2;
    int cp = (lane & 3) * 2;
#pragma unroll
    for (int nt = 0; nt < 8; nt++) {
        int col = nt * 8 + cp;
        int s = col >> 1;
        float bgv = bg[s], biv = bi[s];
        float* gout = g_gates + (size_t)(b * SSDIM + s) * TDIM + t0;
        float* dout = g_drive + (size_t)(b * SSDIM + s) * TDIM + t0;
#pragma unroll
        for (int mt = 0; mt < 4; mt++) {
#pragma unroll
            for (int half = 0; half < 2; half++) {
                int tt = wid * 64 + mt * 16 + r0 + half * 8;
                float ag = c[mt][nt][2 * half]     + bgv;
                float ai = c[mt][nt][2 * half + 1] + biv;
                float g = 1.f / (1.f + __expf(-ag));
                gout[tt] = g;
                dout[tt] = (1.f - g) * ai;
            }
        }
    }
}

// ---------------------------------------------------------------------------
extern "C" void kernel_launch(void* const* d_in, const int* in_sizes, int n_in,
                              void* d_out, int out_size)
{
    const int*   chars    = (const int*)d_in[0];
    const float* emb_byte = (const float*)d_in[1];
    const float* htab     = (const float*)d_in[2];
    const float* Wq       = (const float*)d_in[3];
    const float* bq       = (const float*)d_in[4];
    const float* conv_w   = (const float*)d_in[5];
    const float* conv_b   = (const float*)d_in[6];
    const float* Win      = (const float*)d_in[7];
    const float* b_in     = (const float*)d_in[8];
    const float* Wg       = (const float*)d_in[9];
    const float* bg       = (const float*)d_in[10];
    const float* Wi       = (const float*)d_in[11];
    const float* bi       = (const float*)d_in[12];
    const float* Wo       = (const float*)d_in[13];
    const float* bo       = (const float*)d_in[14];
    const float* lng      = (const float*)d_in[15];
    const float* lnb      = (const float*)d_in[16];
    const float* mlp_w    = (const float*)d_in[17];
    const float* mlp_b    = (const float*)d_in[18];
    const float* Wout     = (const float*)d_in[19];
    const float* bout     = (const float*)d_in[20];
    float* out = (float*)d_out;

    void *p;
    cudaGetSymbolAddress(&p, g_hh);   __half* hh = (__half*)p;
    cudaGetSymbolAddress(&p, g_xh);   __half* xh  = (__half*)p;
    cudaGetSymbolAddress(&p, g_x2h);  __half* x2h = (__half*)p;
    cudaGetSymbolAddress(&p, g_wh);   __half* wh  = (__half*)p;
    cudaGetSymbolAddress(&p, g_feat); __half* feat = (__half*)p;
    cudaGetSymbolAddress(&p, g_wf);   __half* wf  = (__half*)p;

    static int attr_done = 0;
    if (!attr_done) {
        cudaFuncSetAttribute(k_mma<512,8,512,1>, cudaFuncAttributeMaxDynamicSharedMemorySize, SMEM_MM);
        cudaFuncSetAttribute(k_mma<512,8,256,0>, cudaFuncAttributeMaxDynamicSharedMemorySize, SMEM_MM);
        cudaFuncSetAttribute(k_mma<192,3,512,2>, cudaFuncAttributeMaxDynamicSharedMemorySize, SMEM_MM);
        cudaFuncSetAttribute(k_mma_g, cudaFuncAttributeMaxDynamicSharedMemorySize, SMEM_G);
        cudaFuncSetAttribute(k_wo_ln, cudaFuncAttributeMaxDynamicSharedMemorySize, WOLN_SMEM);
        attr_done = 1;
    }

    // weight prep (fp16 transpose)
    k_prep_w<<<512 * 512 / 256, 256>>>(mlp_w,                 512, 0);
    k_prep_w<<<512 * 512 / 256, 256>>>(mlp_w + 512 * 512,     512, 1);
    k_prep_w<<<512 * 512 / 256, 256>>>(mlp_w + 2 * 512 * 512, 512, 2);
    k_prep_w<<<256 * 512 / 256, 256>>>(Wout,                  256, 3);
    k_prep_wf<<<512 * 192 / 256, 256>>>(Win);
    k_prep_wgi<<<64 * 512 / 256, 256>>>(Wg, Wi);

    // fused hash+features
    k_hfeat<<<BT / 32, 256>>>(chars, emb_byte, htab, Wq, bq, conv_w, conv_b);

    dim3 gwin(4, BT / 256);
    // Win: feat @ Win -> silu -> fp16 g_hh
    k_mma<192,3,512,2><<<gwin, 256, SMEM_MM>>>(feat, wf, b_in, 0, hh);

    // gates/drive on tensor cores
    k_mma_g<<<BT / 256, 128, SMEM_G>>>(hh, bg, bi);
    k_scan<<<BDIM * SSDIM, 256>>>();
    k_wo_ln<<<BT / 32, 256, WOLN_SMEM>>>(Wo, bo, lng, lnb);

    dim3 g512(4, BT / 256), g256(2, BT / 256);
    // L1: x = xh -> y1 = x + silu(x@W0+b) -> x2h
    k_mma<512,8,512,1><<<g512, 256, SMEM_MM>>>(xh,
        wh + 0 * (size_t)512 * 512, mlp_b, 0, x2h);
    // L2: x2h -> xh
    k_mma<512,8,512,1><<<g512, 256, SMEM_MM>>>(x2h,
        wh + 1 * (size_t)512 * 512, mlp_b + 512, 0, xh);
    // L3: xh -> x2h
    k_mma<512,8,512,1><<<g512, 256, SMEM_MM>>>(xh,
        wh + 2 * (size_t)512 * 512, mlp_b + 1024, 0, x2h);
    // Wout: x2h -> out f32 [65536,256]
    k_mma<512,8,256,0><<<g256, 256, SMEM_MM>>>(x2h,
        wh + 3 * (size_t)512 * 512, bout, out, 0);
}

// round 17
// speedup vs baseline: 1.0441x; 1.0441x over previous
#include <cuda_runtime.h>
#include <cuda_fp16.h>
#include <math.h>
#include <stdint.h>

#define BDIM 8
#define TDIM 8192
#define BT (BDIM*TDIM)
#define HDIM 512
#define SSDIM 32

typedef unsigned long long u64;

// ---------------- scratch (device globals; no allocations allowed) ----------
__device__ float g_gates[BDIM*SSDIM*TDIM];
__device__ float g_drive[BDIM*SSDIM*TDIM];
__device__ float g_states[BDIM*SSDIM*TDIM];
// fp16 activations
__device__ __half g_hh[(size_t)BT*512];     // fp16 h (post-Win silu)
__device__ __half g_xh[(size_t)BT*512];     // ln output / MLP ping
__device__ __half g_x2h[(size_t)BT*512];    // MLP pong
__device__ __half g_feat[(size_t)BT*192];   // features padded to 192
// fp16 transposed weights
__device__ __half g_wh[4][512*512];         // MLP x3 + Wout
__device__ __half g_wf[512*192];            // Win transposed+padded
__device__ __half g_wgi[64*512];            // [Wg|Wi] interleaved cols

__device__ __forceinline__ float silu_f(float x) { return x / (1.f + __expf(-x)); }

__device__ __forceinline__ u64 pack2(float x) {
    u64 r; asm("mov.b64 %0, {%1, %1};" : "=l"(r) : "f"(x)); return r;
}
__device__ __forceinline__ void ffma2(u64& d, u64 a, u64 b) {
    asm("fma.rn.f32x2 %0, %1, %2, %3;" : "=l"(d) : "l"(a), "l"(b), "l"(d));
}
__device__ __forceinline__ float lo32(u64 v) { return __uint_as_float((unsigned)v); }
__device__ __forceinline__ float hi32(u64 v) { return __uint_as_float((unsigned)(v >> 32)); }

// ---------------- mma.sync / async helpers (arch-agnostic, sm_80+) ----------
__device__ __forceinline__ uint32_t smem_u32(const void* p) {
    uint32_t a;
    asm("{ .reg .u64 t; cvta.to.shared.u64 t, %1; cvt.u32.u64 %0, t; }" : "=r"(a) : "l"(p));
    return a;
}
#define CP_COMMIT()      asm volatile("cp.async.commit_group;" ::: "memory")
#define CP_WAIT1()       asm volatile("cp.async.wait_group 1;" ::: "memory")
#define CP_WAIT0()       asm volatile("cp.async.wait_group 0;" ::: "memory")

__device__ __forceinline__ void cpasync16(uint32_t dst, const void* src) {
    asm volatile("cp.async.cg.shared.global [%0], [%1], 16;" :: "r"(dst), "l"(src));
}
__device__ __forceinline__ void ldmx4(uint32_t* r, uint32_t addr) {
    asm volatile("ldmatrix.sync.aligned.m8n8.x4.shared.b16 {%0,%1,%2,%3}, [%4];"
        : "=r"(r[0]), "=r"(r[1]), "=r"(r[2]), "=r"(r[3]) : "r"(addr));
}
__device__ __forceinline__ void mma16816(float* c, const uint32_t* a,
                                         uint32_t b0, uint32_t b1) {
    asm volatile("mma.sync.aligned.m16n8k16.row.col.f32.f16.f16.f32 "
        "{%0,%1,%2,%3}, {%4,%5,%6,%7}, {%8,%9}, {%0,%1,%2,%3};"
        : "+f"(c[0]), "+f"(c[1]), "+f"(c[2]), "+f"(c[3])
        : "r"(a[0]), "r"(a[1]), "r"(a[2]), "r"(a[3]), "r"(b0), "r"(b1));
}
__device__ __forceinline__ uint32_t tile_addr(uint32_t tbase, int row, int c16) {
    return tbase + row * 128 + ((c16 ^ (row & 7)) << 4);
}

// ---------------------------------------------------------------------------
// K1: FUSED hash/scale-attention + conv/emb/match features -> fp16 g_feat
// block = 32 output tokens; computes 35 haloed hf rows into smem.
// ---------------------------------------------------------------------------
__global__ void __launch_bounds__(256) k_hfeat(
    const int* __restrict__ chars, const float* __restrict__ emb_byte,
    const float* __restrict__ htab, const float* __restrict__ Wq,
    const float* __restrict__ bq,
    const float* __restrict__ conv_w, const float* __restrict__ conv_b)
{
    __shared__ float shf[35 * 64];
    __shared__ float s_be[8][64];
    __shared__ int sch[32];
    int blk = blockIdx.x;
    int b = blk / (TDIM / 32);
    int tBase = (blk % (TDIM / 32)) * 32;
    int tid = threadIdx.x;
    int w = tid >> 5, lane = tid & 31;
    const int* cb = chars + b * TDIM;

    if (tid < 32) sch[tid] = cb[tBase + tid];

    int c0 = lane * 2;
#pragma unroll 1
    for (int it = 0; it < 5; it++) {
        int s = w + it * 8;
        if (s >= 35) break;
        int t = tBase - 3 + s;
        if (t < 0) {
            *(float2*)&shf[s * 64 + c0] = make_float2(0.f, 0.f);
            continue;
        }
        int myc = (lane < 16 && t >= lane) ? cb[t - lane] : 0;
        int acc0 = 0, acc1 = 0, acc2 = 0, acc3 = 0;
        int p = 1;
#pragma unroll
        for (int j = 0; j < 16; j++) {
            int cj = __shfl_sync(0xffffffffu, myc, j);
            int term = cj * p;
            if (j < 2) acc0 += term;
            if (j < 4) acc1 += term;
            if (j < 8) acc2 += term;
            acc3 += term;
            p = (p * 257) & 4095;
        }
        int h0 = acc0 & 4095, h1 = acc1 & 4095, h2 = acc2 & 4095, h3 = acc3 & 4095;

        int ch0 = __shfl_sync(0xffffffffu, myc, 0);
        float2 be = *(const float2*)&emb_byte[ch0 * 64 + c0];
        s_be[w][c0]     = be.x;
        s_be[w][c0 + 1] = be.y;
        __syncwarp();

        float q0 = bq[c0], q1 = bq[c0 + 1];
#pragma unroll 8
        for (int k = 0; k < 64; k++) {
            float bk = s_be[w][k];
            float2 wv = *(const float2*)&Wq[k * 64 + c0];
            q0 = fmaf(bk, wv.x, q0);
            q1 = fmaf(bk, wv.y, q1);
        }
        __syncwarp();

        float2 se0 = *(const float2*)&htab[(size_t)(0 * 4096 + h0) * 64 + c0];
        float2 se1 = *(const float2*)&htab[(size_t)(1 * 4096 + h1) * 64 + c0];
        float2 se2 = *(const float2*)&htab[(size_t)(2 * 4096 + h2) * 64 + c0];
        float2 se3 = *(const float2*)&htab[(size_t)(3 * 4096 + h3) * 64 + c0];

        float s0 = q0 * se0.x + q1 * se0.y;
        float s1 = q0 * se1.x + q1 * se1.y;
        float s2 = q0 * se2.x + q1 * se2.y;
        float s3 = q0 * se3.x + q1 * se3.y;
#pragma unroll
        for (int off = 16; off; off >>= 1) {
            s0 += __shfl_xor_sync(0xffffffffu, s0, off);
            s1 += __shfl_xor_sync(0xffffffffu, s1, off);
            s2 += __shfl_xor_sync(0xffffffffu, s2, off);
            s3 += __shfl_xor_sync(0xffffffffu, s3, off);
        }
        s0 *= 0.125f; s1 *= 0.125f; s2 *= 0.125f; s3 *= 0.125f;
        float m = fmaxf(fmaxf(s0, s1), fmaxf(s2, s3));
        float e0 = __expf(s0 - m), e1 = __expf(s1 - m), e2 = __expf(s2 - m), e3 = __expf(s3 - m);
        float inv = 1.f / (e0 + e1 + e2 + e3);
        float o0 = (e0 * se0.x + e1 * se1.x + e2 * se2.x + e3 * se3.x) * inv;
        float o1 = (e0 * se0.y + e1 * se1.y + e2 * se2.y + e3 * se3.y) * inv;
        *(float2*)&shf[s * 64 + c0] = make_float2(o0, o1);
    }
    __syncthreads();

    // byte emb -> cols 0..63
    for (int idx = tid; idx < 32 * 64; idx += 256) {
        int tok = idx >> 6, c = idx & 63;
        g_feat[(size_t)(b * TDIM + tBase + tok) * 192 + c] =
            __float2half_rn(emb_byte[sch[tok] * 64 + c]);
    }
    // causal conv + silu from smem halo -> cols 64..127
    for (int idx = tid; idx < 32 * 64; idx += 256) {
        int tok = idx >> 6, c = idx & 63;
        float acc = conv_b[c];
#pragma unroll
        for (int k = 0; k < 4; k++)
            acc = fmaf(conv_w[c * 4 + k], shf[(tok + k) * 64 + c], acc);
        g_feat[(size_t)(b * TDIM + tBase + tok) * 192 + 64 + c] =
            __float2half_rn(silu_f(acc));
    }
    // match feats + zero pad -> cols 128..191
    for (int idx = tid; idx < 32 * 64; idx += 256) {
        int tok = idx >> 6, m = idx & 63;
        int t = tBase + tok;
        float v = 0.f;
        if (m < 4) {
            int k = 1 << m;
            if (t >= k) v = (cb[t] == cb[t - k]) ? 1.f : 0.f;
        }
        g_feat[(size_t)(b * TDIM + t) * 192 + 128 + m] = __float2half_rn(v);
    }
}

// ---------------------------------------------------------------------------
// K4: chunk-parallel TinyScan (verified)
// ---------------------------------------------------------------------------
__global__ void __launch_bounds__(256) k_scan()
{
    int bs = blockIdx.x;
    int j = threadIdx.x;
    const float* ga = g_gates + (size_t)bs * TDIM + j * 32;
    const float* dr = g_drive + (size_t)bs * TDIM + j * 32;
    float a[32], bb[32];
#pragma unroll
    for (int i = 0; i < 32; i++) {
        a[i]  = fmaxf(ga[i], 1e-6f);
        bb[i] = dr[i];
    }
    float cumA = 1.f, cumWB = 0.f;
#pragma unroll
    for (int i = 0; i < 32; i++) {
        cumA *= a[i];
        float inv = 1.f / fmaxf(cumA, 1e-8f);
        cumWB = fmaf(bb[i], inv, cumWB);
    }
    __shared__ float sA[256], sB[256];
    sA[j] = cumA;
    sB[j] = cumA * cumWB;
    __syncthreads();
    for (int d = 1; d < 256; d <<= 1) {
        float a2 = sA[j], b2 = sB[j], a1 = 0.f, b1 = 0.f;
        if (j >= d) { a1 = sA[j - d]; b1 = sB[j - d]; }
        __syncthreads();
        if (j >= d) { sA[j] = a2 * a1; sB[j] = fmaf(a2, b1, b2); }
        __syncthreads();
    }
    float hc = (j == 0) ? 0.f : sB[j - 1];
    cumA = 1.f; cumWB = 0.f;
    float* st = g_states + (size_t)bs * TDIM + j * 32;
#pragma unroll
    for (int i = 0; i < 32; i++) {
        cumA *= a[i];
        float inv = 1.f / fmaxf(cumA, 1e-8f);
        cumWB = fmaf(bb[i], inv, cumWB);
        st[i] = cumA * (hc + cumWB);
    }
}

// ---------------------------------------------------------------------------
// K5: fused y = hh + states@Wo + bo, LayerNorm, write fp16 g_xh.
// ---------------------------------------------------------------------------
#define WOLN_SMEM (32*32*4 + 32*520*4)
__global__ void __launch_bounds__(256) k_wo_ln(
    const float* __restrict__ Wo, const float* __restrict__ bo,
    const float* __restrict__ lng, const float* __restrict__ lnb)
{
    extern __shared__ float dyn[];
    float (*sxt)[32] = (float(*)[32])dyn;
    float* sy = dyn + 32 * 32;
    int tid = threadIdx.x;
    int n0 = blockIdx.x * 32;
    int b = n0 / TDIM, t0 = n0 % TDIM;

    for (int i = tid; i < 32 * 8; i += 256) {
        int s = i >> 3, t4 = (i & 7) * 4;
        float4 v = *(const float4*)&g_states[(size_t)(b * SSDIM + s) * TDIM + t0 + t4];
        *(float4*)&sxt[s][t4] = v;
    }
    __syncthreads();

    u64 acc[16][2];
#pragma unroll
    for (int i = 0; i < 16; i++) { acc[i][0] = 0ull; acc[i][1] = 0ull; }

#pragma unroll 1
    for (int k4 = 0; k4 < 32; k4 += 4) {
        u64 wp[4][2];
#pragma unroll
        for (int j = 0; j < 4; j++) {
            wp[j][0] = pack2(Wo[(size_t)(k4 + j) * 512 + tid]);
            wp[j][1] = pack2(Wo[(size_t)(k4 + j) * 512 + tid + 256]);
        }
#pragma unroll
        for (int j = 0; j < 4; j++) {
            const ulonglong2* xr = (const ulonglong2*)&sxt[k4 + j][0];
#pragma unroll
            for (int q = 0; q < 8; q++) {
                ulonglong2 x2 = xr[q];
                ffma2(acc[2 * q][0],     x2.x, wp[j][0]);
                ffma2(acc[2 * q][1],     x2.x, wp[j][1]);
                ffma2(acc[2 * q + 1][0], x2.y, wp[j][0]);
                ffma2(acc[2 * q + 1][1], x2.y, wp[j][1]);
            }
        }
    }
#pragma unroll
    for (int cc = 0; cc < 2; cc++) {
        int col = tid + cc * 256;
        float bv = bo[col];
#pragma unroll
        for (int p = 0; p < 16; p++) {
            size_t r0 = (size_t)(n0 + 2 * p) * 512 + col;
            sy[(2 * p) * 520 + col]     = lo32(acc[p][cc]) + bv + __half2float(g_hh[r0]);
            sy[(2 * p + 1) * 520 + col] = hi32(acc[p][cc]) + bv + __half2float(g_hh[r0 + 512]);
        }
    }
    __syncthreads();

    int wid = tid >> 5, lane = tid & 31;
#pragma unroll
    for (int q = 0; q < 4; q++) {
        int tok = wid * 4 + q;
        const float* row = sy + tok * 520;
        float4 v[4];
        float lsum = 0.f, lsq = 0.f;
#pragma unroll
        for (int i = 0; i < 4; i++) {
            v[i] = *(const float4*)&row[lane * 16 + i * 4];
            lsum += v[i].x + v[i].y + v[i].z + v[i].w;
            lsq  += v[i].x * v[i].x + v[i].y * v[i].y + v[i].z * v[i].z + v[i].w * v[i].w;
        }
#pragma unroll
        for (int off = 16; off; off >>= 1) {
            lsum += __shfl_xor_sync(0xffffffffu, lsum, off);
            lsq  += __shfl_xor_sync(0xffffffffu, lsq,  off);
        }
        float mu = lsum * (1.f / 512.f);
        float var = lsq * (1.f / 512.f) - mu * mu;
        float rstd = rsqrtf(var + 1e-5f);
        __half hh[16];
#pragma unroll
        for (int i = 0; i < 4; i++) {
            float4 g4 = *(const float4*)&lng[lane * 16 + i * 4];
            float4 b4 = *(const float4*)&lnb[lane * 16 + i * 4];
            hh[i * 4 + 0] = __float2half_rn((v[i].x - mu) * rstd * g4.x + b4.x);
            hh[i * 4 + 1] = __float2half_rn((v[i].y - mu) * rstd * g4.y + b4.y);
            hh[i * 4 + 2] = __float2half_rn((v[i].z - mu) * rstd * g4.z + b4.z);
            hh[i * 4 + 3] = __float2half_rn((v[i].w - mu) * rstd * g4.w + b4.w);
        }
        *(int4*)&g_xh[(size_t)(n0 + tok) * 512 + lane * 16]     = *(int4*)&hh[0];
        *(int4*)&g_xh[(size_t)(n0 + tok) * 512 + lane * 16 + 8] = *(int4*)&hh[8];
    }
}

// ---------------------------------------------------------------------------
// Weight prep
// ---------------------------------------------------------------------------
__global__ void __launch_bounds__(256) k_prep_w(
    const float* __restrict__ W, int N, int layer)
{
    int idx = blockIdx.x * 256 + threadIdx.x;
    int k = idx & 511;
    int n = idx >> 9;
    if (n >= N) return;
    float w = W[(size_t)k * N + n];
    g_wh[layer][(size_t)n * 512 + k] = __float2half_rn(w);
}
__global__ void __launch_bounds__(256) k_prep_wf(const float* __restrict__ Win)
{
    int idx = blockIdx.x * 256 + threadIdx.x;
    int k = idx % 192;
    int n = idx / 192;
    if (n >= 512) return;
    float w = (k < 132) ? Win[(size_t)k * 512 + n] : 0.f;
    g_wf[(size_t)n * 192 + k] = __float2half_rn(w);
}
__global__ void __launch_bounds__(256) k_prep_wgi(
    const float* __restrict__ Wg, const float* __restrict__ Wi)
{
    int idx = blockIdx.x * 256 + threadIdx.x;
    int k = idx & 511;
    int n = idx >> 9;
    if (n >= 64) return;
    float w = (n & 1) ? Wi[(size_t)k * 32 + (n >> 1)] : Wg[(size_t)k * 32 + (n >> 1)];
    g_wgi[(size_t)n * 512 + k] = __float2half_rn(w);
}

// ---------------------------------------------------------------------------
// fp16 1-term mma.sync GEMM: D = X16@W16' (fp32 accum)
// CTA: 256xNc128xK(KDIM); 8 warps 4x2, warp tile 64x64.
// 2-stage cp.async double buffer, KT=64 (48KB/stage, 96KB -> 2 CTAs/SM).
// EPI: 0 = v+bias -> yf f32 (stride NOUT)                 [Wout]
//      1 = fp16resid + silu(v+bias) -> yh fp16            [MLP layers]
//      2 = silu(v+bias) -> yh fp16                        [Win]
// ---------------------------------------------------------------------------
#define STAGE_BYTES 49152
#define SMEM_MM (2 * STAGE_BYTES)

template<int KDIM, int NKT, int NOUT, int EPI>
__global__ void __launch_bounds__(256) k_mma(
    const __half* __restrict__ xh,
    const __half* __restrict__ wh,
    const float* __restrict__ bias,
    float* __restrict__ yf, __half* __restrict__ yh)
{
    extern __shared__ char dsm[];
    uint32_t smem0 = smem_u32(dsm);
    int tid = threadIdx.x;
    int wid = tid >> 5, lane = tid & 31;
    int wm = wid >> 1, wn = wid & 1;
    int n0 = blockIdx.x * 128;
    int m0 = blockIdx.y * 256;

    float c[4][8][4];
#pragma unroll
    for (int i = 0; i < 4; i++)
#pragma unroll
        for (int j = 0; j < 8; j++)
#pragma unroll
            for (int e = 0; e < 4; e++) c[i][j][e] = 0.f;

    auto fill = [&](int kt) {
        int stage = kt & 1;
        int kb = kt * 64;
        uint32_t sb = smem0 + stage * STAGE_BYTES;
#pragma unroll
        for (int j = 0; j < 12; j++) {
            int cidx = tid + 256 * j;
            const __half* src;
            uint32_t toff;
            int idx;
            if (cidx < 2048) { idx = cidx;        toff = 0;     src = xh + (size_t)(m0 + (idx >> 3)) * KDIM; }
            else             { idx = cidx - 2048; toff = 32768; src = wh + (size_t)(n0 + (idx >> 3)) * KDIM; }
            int row = idx >> 3;
            int c16 = idx & 7;
            uint32_t dst = sb + toff + row * 128 + ((c16 ^ (row & 7)) << 4);
            cpasync16(dst, (const void*)(src + kb + c16 * 8));
        }
        CP_COMMIT();
    };

    fill(0);

    int la = lane & 15, lh = lane >> 4;

    for (int i = 0; i < NKT; i++) {
        uint32_t sb = smem0 + (i & 1) * STAGE_BYTES;
        if (i + 1 < NKT) { fill(i + 1); CP_WAIT1(); } else { CP_WAIT0(); }
        __syncthreads();

#pragma unroll
        for (int kc = 0; kc < 4; kc++) {
            int c16 = kc * 2 + lh;
            uint32_t ah[4][4];
#pragma unroll
            for (int mt = 0; mt < 4; mt++)
                ldmx4(ah[mt], tile_addr(sb, wm * 64 + mt * 16 + la, c16));
#pragma unroll
            for (int hb = 0; hb < 2; hb++) {
                uint32_t bhf[2][4];
#pragma unroll
                for (int g = 0; g < 2; g++)
                    ldmx4(bhf[g], tile_addr(sb + 32768, wn * 64 + (hb * 2 + g) * 16 + la, c16));
#pragma unroll
                for (int mt = 0; mt < 4; mt++) {
#pragma unroll
                    for (int nt = 0; nt < 4; nt++) {
                        int g = nt >> 1, h = nt & 1;
                        mma16816(c[mt][hb * 4 + nt], ah[mt], bhf[g][h], bhf[g][2 + h]);
                    }
                }
            }
        }
        __syncthreads();
    }

    int r0 = lane >> 2;
    int cp = (lane & 3) * 2;
#pragma unroll
    for (int nt = 0; nt < 8; nt++) {
        int col = n0 + wn * 64 + nt * 8 + cp;
        float2 bv = *(const float2*)&bias[col];
#pragma unroll
        for (int mt = 0; mt < 4; mt++) {
#pragma unroll
            for (int half = 0; half < 2; half++) {
                int row = m0 + wm * 64 + mt * 16 + r0 + half * 8;
                float v0 = c[mt][nt][2 * half]     + bv.x;
                float v1 = c[mt][nt][2 * half + 1] + bv.y;
                if (EPI == 1) {
                    __half2 xr = *(const __half2*)&xh[(size_t)row * KDIM + col];
                    v0 = __half2float(xr.x) + silu_f(v0);
                    v1 = __half2float(xr.y) + silu_f(v1);
                    __half2 hp;
                    hp.x = __float2half_rn(v0);
                    hp.y = __float2half_rn(v1);
                    *(__half2*)&yh[(size_t)row * 512 + col] = hp;
                } else if (EPI == 2) {
                    v0 = silu_f(v0);
                    v1 = silu_f(v1);
                    __half2 hp;
                    hp.x = __float2half_rn(v0);
                    hp.y = __float2half_rn(v1);
                    *(__half2*)&yh[(size_t)row * 512 + col] = hp;
                } else {
                    *(float2*)&yf[(size_t)row * NOUT + col] = make_float2(v0, v1);
                }
            }
        }
    }
}

// ---------------------------------------------------------------------------
// Gates MMA: hh[BT,512] @ wgi[64,512]' -> sigmoid/drive -> (B,S,T) layout
// 2-stage double buffer, 4 warps.
// ---------------------------------------------------------------------------
#define GSTG (32768 + 8192)
#define SMEM_G (2 * GSTG)
__global__ void __launch_bounds__(128) k_mma_g(
    const __half* __restrict__ xh,
    const float* __restrict__ bg, const float* __restrict__ bi)
{
    extern __shared__ char dsm[];
    uint32_t smem0 = smem_u32(dsm);
    int tid = threadIdx.x;
    int wid = tid >> 5, lane = tid & 31;
    int m0 = blockIdx.x * 256;
    int b = m0 / TDIM, t0 = m0 % TDIM;

    float c[4][8][4];
#pragma unroll
    for (int i = 0; i < 4; i++)
#pragma unroll
        for (int j = 0; j < 8; j++)
#pragma unroll
            for (int e = 0; e < 4; e++) c[i][j][e] = 0.f;

    auto fill = [&](int kt) {
        int stage = kt & 1;
        int kb = kt * 64;
        uint32_t sb = smem0 + stage * GSTG;
#pragma unroll
        for (int j = 0; j < 20; j++) {
            int cidx = tid + 128 * j;
            const __half* src;
            uint32_t toff;
            int idx;
            if (cidx < 2048) { idx = cidx;        toff = 0;     src = xh + (size_t)(m0 + (idx >> 3)) * 512; }
            else             { idx = cidx - 2048; toff = 32768; src = g_wgi + (size_t)(idx >> 3) * 512; }
            int row = idx >> 3;
            int c16 = idx & 7;
            uint32_t dst = sb + toff + row * 128 + ((c16 ^ (row & 7)) << 4);
            cpasync16(dst, (const void*)(src + kb + c16 * 8));
        }
        CP_COMMIT();
    };

    fill(0);

    int la = lane & 15, lh = lane >> 4;

    for (int i = 0; i < 8; i++) {
        uint32_t sb = smem0 + (i & 1) * GSTG;
        if (i + 1 < 8) { fill(i + 1); CP_WAIT1(); } else { CP_WAIT0(); }
        __syncthreads();

#pragma unroll
        for (int kc = 0; kc < 4; kc++) {
            int c16 = kc * 2 + lh;
            uint32_t ah[4][4];
#pragma unroll
            for (int mt = 0; mt < 4; mt++)
                ldmx4(ah[mt], tile_addr(sb, wid * 64 + mt * 16 + la, c16));
            uint32_t bhf[4][4];
#pragma unroll
            for (int g = 0; g < 4; g++)
                ldmx4(bhf[g], tile_addr(sb + 32768, g * 16 + la, c16));
#pragma unroll
            for (int mt = 0; mt < 4; mt++) {
#pragma unroll
                for (int nt = 0; nt < 8; nt++) {
                    int g = nt >> 1, h = nt & 1;
                    mma16816(c[mt][nt], ah[mt], bhf[g][h], bhf[g][2 + h]);
                }
            }
        }
        __syncthreads();
    }

    int r0 = lane >> 2;
    int cp = (lane & 3) * 2;
#pragma unroll
    for (int nt = 0; nt < 8; nt++) {
        int col = nt * 8 + cp;
        int s = col >> 1;
        float bgv = bg[s], biv = bi[s];
        float* gout = g_gates + (size_t)(b * SSDIM + s) * TDIM + t0;
        float* dout = g_drive + (size_t)(b * SSDIM + s) * TDIM + t0;
#pragma unroll
        for (int mt = 0; mt < 4; mt++) {
#pragma unroll
            for (int half = 0; half < 2; half++) {
                int tt = wid * 64 + mt * 16 + r0 + half * 8;
                float ag = c[mt][nt][2 * half]     + bgv;
                float ai = c[mt][nt][2 * half + 1] + biv;
                float g = 1.f / (1.f + __expf(-ag));
                gout[tt] = g;
                dout[tt] = (1.f - g) * ai;
            }
        }
    }
}

// ---------------------------------------------------------------------------
extern "C" void kernel_launch(void* const* d_in, const int* in_sizes, int n_in,
                              void* d_out, int out_size)
{
    const int*   chars    = (const int*)d_in[0];
    const float* emb_byte = (const float*)d_in[1];
    const float* htab     = (const float*)d_in[2];
    const float* Wq       = (const float*)d_in[3];
    const float* bq       = (const float*)d_in[4];
    const float* conv_w   = (const float*)d_in[5];
    const float* conv_b   = (const float*)d_in[6];
    const float* Win      = (const float*)d_in[7];
    const float* b_in     = (const float*)d_in[8];
    const float* Wg       = (const float*)d_in[9];
    const float* bg       = (const float*)d_in[10];
    const float* Wi       = (const float*)d_in[11];
    const float* bi       = (const float*)d_in[12];
    const float* Wo       = (const float*)d_in[13];
    const float* bo       = (const float*)d_in[14];
    const float* lng      = (const float*)d_in[15];
    const float* lnb      = (const float*)d_in[16];
    const float* mlp_w    = (const float*)d_in[17];
    const float* mlp_b    = (const float*)d_in[18];
    const float* Wout     = (const float*)d_in[19];
    const float* bout     = (const float*)d_in[20];
    float* out = (float*)d_out;

    void *p;
    cudaGetSymbolAddress(&p, g_hh);   __half* hh = (__half*)p;
    cudaGetSymbolAddress(&p, g_xh);   __half* xh  = (__half*)p;
    cudaGetSymbolAddress(&p, g_x2h);  __half* x2h = (__half*)p;
    cudaGetSymbolAddress(&p, g_wh);   __half* wh  = (__half*)p;
    cudaGetSymbolAddress(&p, g_feat); __half* feat = (__half*)p;
    cudaGetSymbolAddress(&p, g_wf);   __half* wf  = (__half*)p;

    static int attr_done = 0;
    if (!attr_done) {
        cudaFuncSetAttribute(k_mma<512,8,512,1>, cudaFuncAttributeMaxDynamicSharedMemorySize, SMEM_MM);
        cudaFuncSetAttribute(k_mma<512,8,256,0>, cudaFuncAttributeMaxDynamicSharedMemorySize, SMEM_MM);
        cudaFuncSetAttribute(k_mma<192,3,512,2>, cudaFuncAttributeMaxDynamicSharedMemorySize, SMEM_MM);
        cudaFuncSetAttribute(k_mma_g, cudaFuncAttributeMaxDynamicSharedMemorySize, SMEM_G);
        cudaFuncSetAttribute(k_wo_ln, cudaFuncAttributeMaxDynamicSharedMemorySize, WOLN_SMEM);
        attr_done = 1;
    }

    // weight prep (fp16 transpose)
    k_prep_w<<<512 * 512 / 256, 256>>>(mlp_w,                 512, 0);
    k_prep_w<<<512 * 512 / 256, 256>>>(mlp_w + 512 * 512,     512, 1);
    k_prep_w<<<512 * 512 / 256, 256>>>(mlp_w + 2 * 512 * 512, 512, 2);
    k_prep_w<<<256 * 512 / 256, 256>>>(Wout,                  256, 3);
    k_prep_wf<<<512 * 192 / 256, 256>>>(Win);
    k_prep_wgi<<<64 * 512 / 256, 256>>>(Wg, Wi);

    // fused hash+features
    k_hfeat<<<BT / 32, 256>>>(chars, emb_byte, htab, Wq, bq, conv_w, conv_b);

    dim3 gwin(4, BT / 256);
    // Win: feat @ Win -> silu -> fp16 g_hh
    k_mma<192,3,512,2><<<gwin, 256, SMEM_MM>>>(feat, wf, b_in, 0, hh);

    // gates/drive on tensor cores
    k_mma_g<<<BT / 256, 128, SMEM_G>>>(hh, bg, bi);
    k_scan<<<BDIM * SSDIM, 256>>>();
    k_wo_ln<<<BT / 32, 256, WOLN_SMEM>>>(Wo, bo, lng, lnb);

    dim3 g512(4, BT / 256), g256(2, BT / 256);
    // L1: x = xh -> y1 = x + silu(x@W0+b) -> x2h
    k_mma<512,8,512,1><<<g512, 256, SMEM_MM>>>(xh,
        wh + 0 * (size_t)512 * 512, mlp_b, 0, x2h);
    // L2: x2h -> xh
    k_mma<512,8,512,1><<<g512, 256, SMEM_MM>>>(x2h,
        wh + 1 * (size_t)512 * 512, mlp_b + 512, 0, xh);
    // L3: xh -> x2h
    k_mma<512,8,512,1><<<g512, 256, SMEM_MM>>>(xh,
        wh + 2 * (size_t)512 * 512, mlp_b + 1024, 0, x2h);
    // Wout: x2h -> out f32 [65536,256]
    k_mma<512,8,256,0><<<g256, 256, SMEM_MM>>>(x2h,
        wh + 3 * (size_t)512 * 512, bout, out, 0);
}